// round 2
// baseline (speedup 1.0000x reference)
#include <cuda_runtime.h>
#include <cstdint>

#define T_LEN   1000000
#define HIDDEN  75
#define NS      16
#define BS      64                 // steps per checkpoint block
#define NBLK    (T_LEN / BS)       // 15625
#define RB      8                  // ring blocks (smem)

// Scratch: negated log-priors (np = -prior), and 8-state checkpoints.
__device__ float g_np[T_LEN * 16];     // 64 MB
__device__ float g_ckpt[NBLK * 8];     // 500 KB

// ---------------- packed helpers ----------------
__device__ __forceinline__ unsigned long long addx2(unsigned long long a, unsigned long long b) {
    unsigned long long r;
    asm("add.rn.f32x2 %0, %1, %2;" : "=l"(r) : "l"(a), "l"(b));
    return r;
}
__device__ __forceinline__ float hmin2(unsigned long long w) {
    float lo, hi;
    asm("mov.b64 {%0,%1}, %2;" : "=f"(lo), "=f"(hi) : "l"(w));
    return fminf(lo, hi);
}
__device__ __forceinline__ unsigned long long packx2(float lo, float hi) {
    unsigned long long r;
    asm("mov.b64 %0, {%1,%2};" : "=l"(r) : "f"(lo), "f"(hi));
    return r;
}
__device__ __forceinline__ int ld_acq(const int* p) {
    int v;
    asm volatile("ld.acquire.cta.b32 %0, [%1];" : "=r"(v) : "l"(p) : "memory");
    return v;
}
__device__ __forceinline__ void st_rel(int* p, int v) {
    asm volatile("st.release.cta.b32 [%0], %1;" :: "l"(p), "r"(v) : "memory");
}

// ================= K1: priors =================
// np[t][i] = logsumexp_shift - (logits[i] - max)   (negated log_softmax),
// replaying the reference op order: mul+add+relu, fma-accumulate ascending j,
// +b2, max, shift, sequential exp-sum, log.
__global__ void k_priors(const float* __restrict__ rx,
                         const float* __restrict__ W1,
                         const float* __restrict__ b1,
                         const float* __restrict__ W2,
                         const float* __restrict__ b2,
                         int T) {
    __shared__ float sW1[HIDDEN], sb1[HIDDEN], sW2[HIDDEN * NS], sb2[NS];
    for (int i = threadIdx.x; i < HIDDEN; i += blockDim.x) { sW1[i] = W1[i]; sb1[i] = b1[i]; }
    for (int i = threadIdx.x; i < HIDDEN * NS; i += blockDim.x) sW2[i] = W2[i];
    if (threadIdx.x < NS) sb2[threadIdx.x] = b2[threadIdx.x];
    __syncthreads();

    int t = blockIdx.x * blockDim.x + threadIdx.x;
    if (t >= T) return;

    float x = rx[t];
    float acc[NS];
#pragma unroll
    for (int i = 0; i < NS; i++) acc[i] = 0.0f;

    for (int j = 0; j < HIDDEN; j++) {
        float h = __fadd_rn(__fmul_rn(x, sW1[j]), sb1[j]);
        h = fmaxf(h, 0.0f);
#pragma unroll
        for (int i = 0; i < NS; i++) acc[i] = fmaf(h, sW2[j * NS + i], acc[i]);
    }
#pragma unroll
    for (int i = 0; i < NS; i++) acc[i] = __fadd_rn(acc[i], sb2[i]);

    float m = acc[0];
#pragma unroll
    for (int i = 1; i < NS; i++) m = fmaxf(m, acc[i]);

    float sh[NS];
    float s = 0.0f;
#pragma unroll
    for (int i = 0; i < NS; i++) {
        sh[i] = __fadd_rn(acc[i], -m);
        s = __fadd_rn(s, expf(sh[i]));
    }
    float L = logf(s);

    float* dst = g_np + (size_t)t * NS;
#pragma unroll
    for (int i = 0; i < NS; i++) dst[i] = __fadd_rn(L, -sh[i]);   // -prior
}

// ================= K2: exact sequential scan =================
// Warp 0: 8-state packed-f32x2 scan + checkpoints. Warps 1-3: stage priors
// global->smem ring (each warp owns its own SMSP, spins cost no scan issue slots).
__global__ void __launch_bounds__(128, 1) k_scan() {
    __shared__ __align__(16) float ring[RB * BS * 16];   // 32 KB
    __shared__ int flag[RB];
    __shared__ int consumed;

    const int tid  = threadIdx.x;
    const int wid  = tid >> 5;
    const int lane = tid & 31;

    if (tid < RB) flag[tid] = 0;
    if (tid == 0) consumed = 0;
    __syncthreads();

    if (wid == 0) {
        unsigned long long P01 = 0ull, P23 = 0ull, P45 = 0ull, P67 = 0ull; // zeros = (0.f,0.f)
        for (int b = 0; b < NBLK; b++) {
            if (lane == 0) {
                float* cp = g_ckpt + (size_t)b * 8;
                asm volatile("st.global.v2.u64 [%0], {%1,%2};" :: "l"(cp),     "l"(P01), "l"(P23) : "memory");
                asm volatile("st.global.v2.u64 [%0], {%1,%2};" :: "l"(cp + 4), "l"(P45), "l"(P67) : "memory");
            }
            while (ld_acq(&flag[b & (RB - 1)]) != b + 1) { }
            const float* base = &ring[(b & (RB - 1)) * (BS * 16)];
#pragma unroll
            for (int k = 0; k < BS; k++) {
                const ulonglong2 A = *(const ulonglong2*)(base + k * 16);      // np0..3
                const ulonglong2 B = *(const ulonglong2*)(base + k * 16 + 4);  // np4..7
                const ulonglong2 C = *(const ulonglong2*)(base + k * 16 + 8);  // np8..11
                const ulonglong2 D = *(const ulonglong2*)(base + k * 16 + 12); // np12..15
                unsigned long long w0 = addx2(P01, A.x);
                unsigned long long w1 = addx2(P23, A.y);
                unsigned long long w2 = addx2(P45, B.x);
                unsigned long long w3 = addx2(P67, B.y);
                unsigned long long w4 = addx2(P01, C.x);
                unsigned long long w5 = addx2(P23, C.y);
                unsigned long long w6 = addx2(P45, D.x);
                unsigned long long w7 = addx2(P67, D.y);
                float o0 = hmin2(w0), o1 = hmin2(w1), o2 = hmin2(w2), o3 = hmin2(w3);
                float o4 = hmin2(w4), o5 = hmin2(w5), o6 = hmin2(w6), o7 = hmin2(w7);
                P01 = packx2(o0, o1);
                P23 = packx2(o2, o3);
                P45 = packx2(o4, o5);
                P67 = packx2(o6, o7);
            }
            __syncwarp();
            if (lane == 0) st_rel(&consumed, b + 1);
        }
    } else {
        // copier warps: wid 1..3 handle blocks b with b % 3 == wid-1
        for (int b = wid - 1; b < NBLK; b += 3) {
            while (b >= RB && ld_acq(&consumed) < b - RB + 1) __nanosleep(100);
            const float4* src = (const float4*)(g_np + (size_t)b * (BS * 16));
            float4* dst = (float4*)&ring[(b & (RB - 1)) * (BS * 16)];
#pragma unroll
            for (int r = 0; r < 8; r++) dst[r * 32 + lane] = src[r * 32 + lane];
            __syncwarp();
            if (lane == 0) st_rel(&flag[b & (RB - 1)], b + 1);
        }
    }
}

// ================= K3: parallel det/conf emission =================
// Each thread replays one 64-step chunk bit-exactly from its checkpoint.
__global__ void k_emit(float* __restrict__ out_det, float* __restrict__ out_conf) {
    int c = blockIdx.x * blockDim.x + threadIdx.x;
    if (c >= NBLK) return;

    float p[8];
    float4 a = *(const float4*)(g_ckpt + (size_t)c * 8);
    float4 b = *(const float4*)(g_ckpt + (size_t)c * 8 + 4);
    p[0] = a.x; p[1] = a.y; p[2] = a.z; p[3] = a.w;
    p[4] = b.x; p[5] = b.y; p[6] = b.z; p[7] = b.w;

    const float* np = g_np + (size_t)c * (BS * 16);
    const int tbase = c * BS;

    for (int k = 0; k < BS; k++) {
        // det: first-index argmin over p[0..7], parity
        float best = p[0];
        int idx = 0;
#pragma unroll
        for (int j = 1; j < 8; j++) {
            if (p[j] < best) { best = p[j]; idx = j; }
        }
        // conf: S = sum_{j=0..15} exp(pmin - p_j) with duplicated halves,
        // sequential ascending; 2*conf = 2*(1/S)
        float e[8];
#pragma unroll
        for (int j = 0; j < 8; j++) e[j] = expf(__fadd_rn(best, -p[j]));
        float S = e[0];
#pragma unroll
        for (int j = 1; j < 8; j++) S = __fadd_rn(S, e[j]);
#pragma unroll
        for (int j = 0; j < 8; j++) S = __fadd_rn(S, e[j]);
        float conf = __fdiv_rn(1.0f, S);

        out_det[tbase + k]  = (float)(idx & 1);
        out_conf[tbase + k] = __fmul_rn(2.0f, conf);

        // update (identical arithmetic to K2's packed ops)
        const float* q = np + k * 16;
        float4 q0 = *(const float4*)(q);
        float4 q1 = *(const float4*)(q + 4);
        float4 q2 = *(const float4*)(q + 8);
        float4 q3 = *(const float4*)(q + 12);
        float nv[16] = { q0.x, q0.y, q0.z, q0.w,  q1.x, q1.y, q1.z, q1.w,
                         q2.x, q2.y, q2.z, q2.w,  q3.x, q3.y, q3.z, q3.w };
        float newp[8];
#pragma unroll
        for (int i = 0; i < 8; i++) {
            int a2 = (2 * i) & 7;
            newp[i] = fminf(__fadd_rn(p[a2],     nv[2 * i]),
                            __fadd_rn(p[a2 + 1], nv[2 * i + 1]));
        }
#pragma unroll
        for (int i = 0; i < 8; i++) p[i] = newp[i];
    }
}

// ================= launch =================
extern "C" void kernel_launch(void* const* d_in, const int* in_sizes, int n_in,
                              void* d_out, int out_size) {
    const float* rx = (const float*)d_in[0];
    const float* W1 = (const float*)d_in[1];
    const float* b1 = (const float*)d_in[2];
    const float* W2 = (const float*)d_in[3];
    const float* b2 = (const float*)d_in[4];
    float* out = (float*)d_out;

    int T = in_sizes[0];
    if (T > T_LEN) T = T_LEN;

    k_priors<<<(T + 255) / 256, 256>>>(rx, W1, b1, W2, b2, T);
    k_scan<<<1, 128>>>();
    k_emit<<<(NBLK + 127) / 128, 128>>>(out, out + T);
}